// round 2
// baseline (speedup 1.0000x reference)
#include <cuda_runtime.h>

// ---- problem constants ----
#define NN        100000
#define NE        1600000
#define PER_GRAPH 100
#define N_GRAPHS  1000
#define POOL_K    30
#define C3        64

// ---- device scratch (no allocations allowed) ----
static __device__ float g_bufA[NN * 128];     // GEMM output (xw)
static __device__ float g_bufB[NN * 128];     // layer output
static __device__ float g_dinv[NN];
static __device__ int   g_count[NN];
static __device__ int   g_rowPtr[NN + 1];
static __device__ int   g_cursor[NN];
static __device__ int   g_csrSrc[NE];
static __device__ int   g_idx64;              // 1 if edge_index is int64, 0 if int32

// ---------------- dtype probe ----------------
// int64 little-endian: value v<2^31 -> words [v, 0]. If the first 64 odd words
// are all zero, indices are int64; otherwise int32.
__global__ void k_detect(const void* __restrict__ ei) {
    if (threadIdx.x == 0 && blockIdx.x == 0) {
        const int* w = (const int*)ei;
        int is64 = 1;
        for (int i = 0; i < 64; i++)
            if (w[2 * i + 1] != 0) { is64 = 0; break; }
        g_idx64 = is64;
    }
}

__device__ __forceinline__ int edge_at(const void* p, long long i) {
    return g_idx64 ? (int)((const long long*)p)[i] : ((const int*)p)[i];
}

// ---------------- CSR build ----------------
__global__ void k_zero_counts() {
    int i = blockIdx.x * blockDim.x + threadIdx.x;
    if (i < NN) g_count[i] = 0;
}

__global__ void k_count(const void* __restrict__ ei, int e) {
    int i = blockIdx.x * blockDim.x + threadIdx.x;
    if (i >= e) return;
    int d = edge_at(ei, (long long)e + i);   // dst half
    if ((unsigned)d < NN) atomicAdd(&g_count[d], 1);
}

// single block, 1024 threads: exclusive scan of counts -> rowPtr/cursor, dinv
__global__ void k_scan(int n) {
    __shared__ int ssum[1024];
    const int t = threadIdx.x;
    const int chunk = (n + 1023) / 1024;
    int lo = t * chunk;
    int hi = lo + chunk; if (hi > n) hi = n;
    int s = 0;
    for (int i = lo; i < hi; i++) s += g_count[i];
    ssum[t] = s;
    __syncthreads();
    for (int off = 1; off < 1024; off <<= 1) {
        int v = (t >= off) ? ssum[t - off] : 0;
        __syncthreads();
        ssum[t] += v;
        __syncthreads();
    }
    int run = (t == 0) ? 0 : ssum[t - 1];
    for (int i = lo; i < hi; i++) {
        g_rowPtr[i] = run;
        g_cursor[i] = run;
        int c = g_count[i];
        g_dinv[i] = rsqrtf((float)c + 1.0f);   // +1 self-loop
        run += c;
    }
    if (t == 1023) g_rowPtr[n] = run;
}

__global__ void k_fill(const void* __restrict__ ei, int e) {
    int i = blockIdx.x * blockDim.x + threadIdx.x;
    if (i >= e) return;
    int s = edge_at(ei, i);
    int d = edge_at(ei, (long long)e + i);
    if ((unsigned)s >= NN || (unsigned)d >= NN) return;
    int pos = atomicAdd(&g_cursor[d], 1);
    if ((unsigned)pos < NE) g_csrSrc[pos] = s;
}

// ---------------- GEMM: bufA[n x C] = X[n x 128] @ W[128 x C] ----------------
// 64-row tile, 256 threads, 4x(C/16) register tile per thread. Static smem <48KB.
template <int C, int SRC>   // SRC: 0 = param X, 1 = g_bufB
__global__ void __launch_bounds__(256) k_gemm(const float* __restrict__ Xin,
                                              const float* __restrict__ W, int n) {
    __shared__ float xs[64 * 129];     // padded rows (bank-conflict-free)
    __shared__ float Wsh[16 * C];      // K-chunk of W
    const float* __restrict__ X = SRC ? (const float*)g_bufB : Xin;
    float* __restrict__ Y = g_bufA;

    const int tid = threadIdx.x;
    const int tx = tid & 15, ty = tid >> 4;
    const int row0 = blockIdx.x * 64;
    constexpr int CC  = C / 16;   // cols per thread (8 or 4)
    constexpr int CC4 = CC / 4;   // float4s per thread (2 or 1)

    // load X tile (64 x 128), zero-pad OOB rows
    for (int i = tid; i < 64 * 32; i += 256) {
        int r = i >> 5, c4 = i & 31;
        float4 v = make_float4(0.f, 0.f, 0.f, 0.f);
        if (row0 + r < n) v = ((const float4*)X)[(long long)(row0 + r) * 32 + c4];
        float* p = &xs[r * 129 + c4 * 4];
        p[0] = v.x; p[1] = v.y; p[2] = v.z; p[3] = v.w;
    }

    float4 acc[4][CC4];
#pragma unroll
    for (int a = 0; a < 4; a++)
#pragma unroll
        for (int b = 0; b < CC4; b++) acc[a][b] = make_float4(0.f, 0.f, 0.f, 0.f);

    for (int kc = 0; kc < 8; kc++) {
        __syncthreads();
        for (int i = tid; i < 16 * C / 4; i += 256)
            ((float4*)Wsh)[i] = ((const float4*)W)[kc * (16 * C / 4) + i];
        __syncthreads();
#pragma unroll
        for (int k = 0; k < 16; k++) {
            float xr[4];
#pragma unroll
            for (int rr = 0; rr < 4; rr++)
                xr[rr] = xs[(ty + 16 * rr) * 129 + kc * 16 + k];
            float4 wv[CC4];
#pragma unroll
            for (int q = 0; q < CC4; q++)
                wv[q] = *(const float4*)&Wsh[k * C + tx * CC + 4 * q];
#pragma unroll
            for (int rr = 0; rr < 4; rr++)
#pragma unroll
                for (int q = 0; q < CC4; q++) {
                    acc[rr][q].x = fmaf(xr[rr], wv[q].x, acc[rr][q].x);
                    acc[rr][q].y = fmaf(xr[rr], wv[q].y, acc[rr][q].y);
                    acc[rr][q].z = fmaf(xr[rr], wv[q].z, acc[rr][q].z);
                    acc[rr][q].w = fmaf(xr[rr], wv[q].w, acc[rr][q].w);
                }
        }
    }

#pragma unroll
    for (int rr = 0; rr < 4; rr++) {
        int row = row0 + ty + 16 * rr;
        if (row < n) {
#pragma unroll
            for (int q = 0; q < CC4; q++)
                ((float4*)Y)[(long long)row * (C / 4) + tx * CC4 + q] = acc[rr][q];
        }
    }
}

// ---------------- aggregation (fused self-loop + bias + optional ReLU) ----------------
// out[i] = relu( xw[i]*dinv[i]^2 + b + sum_{s in N(i)} xw[s]*dinv[s]*dinv[i] )
template <bool RELU>
__global__ void __launch_bounds__(256) k_agg128(const float* __restrict__ bias) {
    int warp = (blockIdx.x * 256 + threadIdx.x) >> 5;
    int lane = threadIdx.x & 31;
    if (warp >= NN) return;
    const float4* __restrict__ xw = (const float4*)g_bufA;
    const float d  = g_dinv[warp];
    const float dd = d * d;
    float4 bv  = ((const float4*)bias)[lane];
    float4 acc = xw[(long long)warp * 32 + lane];
    acc.x = fmaf(acc.x, dd, bv.x); acc.y = fmaf(acc.y, dd, bv.y);
    acc.z = fmaf(acc.z, dd, bv.z); acc.w = fmaf(acc.w, dd, bv.w);

    int j = g_rowPtr[warp];
    const int end = g_rowPtr[warp + 1];
    for (; j + 1 < end; j += 2) {
        int s0 = g_csrSrc[j], s1 = g_csrSrc[j + 1];
        float n0 = g_dinv[s0] * d, n1 = g_dinv[s1] * d;
        float4 v0 = xw[(long long)s0 * 32 + lane];
        float4 v1 = xw[(long long)s1 * 32 + lane];
        acc.x += v0.x * n0 + v1.x * n1;
        acc.y += v0.y * n0 + v1.y * n1;
        acc.z += v0.z * n0 + v1.z * n1;
        acc.w += v0.w * n0 + v1.w * n1;
    }
    if (j < end) {
        int s0 = g_csrSrc[j];
        float n0 = g_dinv[s0] * d;
        float4 v0 = xw[(long long)s0 * 32 + lane];
        acc.x += v0.x * n0; acc.y += v0.y * n0;
        acc.z += v0.z * n0; acc.w += v0.w * n0;
    }
    if (RELU) {
        acc.x = fmaxf(acc.x, 0.f); acc.y = fmaxf(acc.y, 0.f);
        acc.z = fmaxf(acc.z, 0.f); acc.w = fmaxf(acc.w, 0.f);
    }
    ((float4*)g_bufB)[(long long)warp * 32 + lane] = acc;
}

__global__ void __launch_bounds__(256) k_agg64(const float* __restrict__ bias) {
    int warp = (blockIdx.x * 256 + threadIdx.x) >> 5;
    int lane = threadIdx.x & 31;
    if (warp >= NN) return;
    const float2* __restrict__ xw = (const float2*)g_bufA;
    const float d  = g_dinv[warp];
    const float dd = d * d;
    float2 bv  = ((const float2*)bias)[lane];
    float2 acc = xw[(long long)warp * 32 + lane];
    acc.x = fmaf(acc.x, dd, bv.x); acc.y = fmaf(acc.y, dd, bv.y);

    int j = g_rowPtr[warp];
    const int end = g_rowPtr[warp + 1];
    for (; j + 1 < end; j += 2) {
        int s0 = g_csrSrc[j], s1 = g_csrSrc[j + 1];
        float n0 = g_dinv[s0] * d, n1 = g_dinv[s1] * d;
        float2 v0 = xw[(long long)s0 * 32 + lane];
        float2 v1 = xw[(long long)s1 * 32 + lane];
        acc.x += v0.x * n0 + v1.x * n1;
        acc.y += v0.y * n0 + v1.y * n1;
    }
    if (j < end) {
        int s0 = g_csrSrc[j];
        float n0 = g_dinv[s0] * d;
        float2 v0 = xw[(long long)s0 * 32 + lane];
        acc.x += v0.x * n0; acc.y += v0.y * n0;
    }
    ((float2*)g_bufB)[(long long)warp * 32 + lane] = acc;
}

// ---------------- sort pool ----------------
// One block per graph; stable descending rank by last channel (matches argsort(-key)).
__global__ void k_sortpool(float* __restrict__ out) {
    __shared__ float key[PER_GRAPH];
    __shared__ int   sel[POOL_K];
    const int g = blockIdx.x;
    const int tid = threadIdx.x;
    const float* __restrict__ h = g_bufB;

    if (tid < PER_GRAPH)
        key[tid] = h[((long long)(g * PER_GRAPH + tid)) * C3 + (C3 - 1)];
    __syncthreads();

    if (tid < PER_GRAPH) {
        float ki = key[tid];
        int rank = 0;
#pragma unroll 4
        for (int j = 0; j < PER_GRAPH; j++) {
            float kj = key[j];
            rank += (kj > ki) || (kj == ki && j < tid);
        }
        if (rank < POOL_K) sel[rank] = tid;
    }
    __syncthreads();

    for (int t = tid; t < POOL_K * C3; t += blockDim.x) {
        int rank = t / C3, c = t % C3;
        int node = sel[rank];
        out[(long long)g * (POOL_K * C3) + t] =
            h[((long long)(g * PER_GRAPH + node)) * C3 + c];
    }
}

// ---------------- launch ----------------
extern "C" void kernel_launch(void* const* d_in, const int* in_sizes, int n_in,
                              void* d_out, int out_size) {
    const float* x  = (const float*)d_in[0];
    const void*  ei = d_in[1];            // int32 or int64, probed on device
    const float* W1 = (const float*)d_in[3];
    const float* b1 = (const float*)d_in[4];
    const float* W2 = (const float*)d_in[5];
    const float* b2 = (const float*)d_in[6];
    const float* W3 = (const float*)d_in[7];
    const float* b3 = (const float*)d_in[8];
    float* out = (float*)d_out;

    const int n = in_sizes[0] / 128;   // 100000
    const int e = in_sizes[1] / 2;     // 1600000
    const int T = 256;

    // CSR build (recomputed every call; deterministic)
    k_detect<<<1, 32>>>(ei);
    k_zero_counts<<<(NN + T - 1) / T, T>>>();
    k_count<<<(e + T - 1) / T, T>>>(ei, e);
    k_scan<<<1, 1024>>>(n);
    k_fill<<<(e + T - 1) / T, T>>>(ei, e);

    const int gemmBlocks = (n + 63) / 64;
    const int aggBlocks  = (NN * 32 + T - 1) / T;   // warp per node

    // Layer 1: 128 -> 128, relu
    k_gemm<128, 0><<<gemmBlocks, T>>>(x, W1, n);
    k_agg128<true><<<aggBlocks, T>>>(b1);
    // Layer 2: 128 -> 128, relu
    k_gemm<128, 1><<<gemmBlocks, T>>>(nullptr, W2, n);
    k_agg128<true><<<aggBlocks, T>>>(b2);
    // Layer 3: 128 -> 64, no relu
    k_gemm<64, 1><<<gemmBlocks, T>>>(nullptr, W3, n);
    k_agg64<<<aggBlocks, T>>>(b3);

    // Sort pool
    k_sortpool<<<N_GRAPHS, 128>>>(out);
}

// round 3
// speedup vs baseline: 1.3072x; 1.3072x over previous
#include <cuda_runtime.h>

// ---- problem constants ----
#define NN        100000
#define NE        1600000
#define PER_GRAPH 100
#define N_GRAPHS  1000
#define POOL_K    30
#define C3        64
#define SCAN_BLKS ((NN + 1023) / 1024)   // 98

// ---- device scratch (no allocations allowed) ----
static __device__ float g_bufA[NN * 128];     // GEMM output (xw)
static __device__ float g_bufB[NN * 128];     // layer output
static __device__ float g_dinv[NN];
static __device__ int   g_count[NN];
static __device__ int   g_rowPtr[NN + 1];
static __device__ int   g_cursor[NN];
static __device__ int   g_csrSrc[NE];
static __device__ int   g_bsum[128];
static __device__ int   g_boff[128];
static __device__ int   g_idx64;              // 1 if edge_index is int64, 0 if int32

// ---------------- dtype probe ----------------
__global__ void k_detect(const void* __restrict__ ei) {
    if (threadIdx.x == 0 && blockIdx.x == 0) {
        const int* w = (const int*)ei;
        int is64 = 1;
        for (int i = 0; i < 64; i++)
            if (w[2 * i + 1] != 0) { is64 = 0; break; }
        g_idx64 = is64;
    }
}

__device__ __forceinline__ int edge_at(const void* p, long long i) {
    return g_idx64 ? (int)((const long long*)p)[i] : ((const int*)p)[i];
}

// ---------------- CSR build ----------------
__global__ void k_zero_counts() {
    int i = blockIdx.x * blockDim.x + threadIdx.x;
    if (i < NN) g_count[i] = 0;
}

__global__ void k_count(const void* __restrict__ ei, int e) {
    int i = blockIdx.x * blockDim.x + threadIdx.x;
    if (i >= e) return;
    int d = edge_at(ei, (long long)e + i);   // dst half
    if ((unsigned)d < NN) atomicAdd(&g_count[d], 1);
}

// Phase A: per-block inclusive scan of counts; local exclusive -> rowPtr
__global__ void __launch_bounds__(1024) k_scanA() {
    __shared__ int s[1024];
    const int tid = threadIdx.x;
    const int i = blockIdx.x * 1024 + tid;
    int c = (i < NN) ? g_count[i] : 0;
    s[tid] = c;
    __syncthreads();
#pragma unroll
    for (int off = 1; off < 1024; off <<= 1) {
        int v = (tid >= off) ? s[tid - off] : 0;
        __syncthreads();
        s[tid] += v;
        __syncthreads();
    }
    if (i < NN) g_rowPtr[i] = s[tid] - c;
    if (tid == 1023) g_bsum[blockIdx.x] = s[1023];
}

// Phase B: scan 98 block totals (single warp-ish block)
__global__ void k_scanB(int nblk) {
    __shared__ int s[128];
    const int tid = threadIdx.x;
    int v = (tid < nblk) ? g_bsum[tid] : 0;
    s[tid] = v;
    __syncthreads();
#pragma unroll
    for (int off = 1; off < 128; off <<= 1) {
        int u = (tid >= off) ? s[tid - off] : 0;
        __syncthreads();
        s[tid] += u;
        __syncthreads();
    }
    if (tid < nblk) g_boff[tid] = s[tid] - v;
    if (tid == 127) g_rowPtr[NN] = s[127];
}

// Phase C: add block offsets, init cursor, compute dinv
__global__ void k_scanC() {
    int i = blockIdx.x * blockDim.x + threadIdx.x;
    if (i >= NN) return;
    int base = g_rowPtr[i] + g_boff[i >> 10];
    g_rowPtr[i] = base;
    g_cursor[i] = base;
    g_dinv[i] = rsqrtf((float)g_count[i] + 1.0f);   // +1 self-loop
}

__global__ void k_fill(const void* __restrict__ ei, int e) {
    int i = blockIdx.x * blockDim.x + threadIdx.x;
    if (i >= e) return;
    int s = edge_at(ei, i);
    int d = edge_at(ei, (long long)e + i);
    if ((unsigned)s >= NN || (unsigned)d >= NN) return;
    int pos = atomicAdd(&g_cursor[d], 1);
    if ((unsigned)pos < NE) g_csrSrc[pos] = s;
}

// ---------------- GEMM: bufA[n x C] = X[n x 128] @ W[128 x C] ----------------
template <int C, int SRC>   // SRC: 0 = param X, 1 = g_bufB
__global__ void __launch_bounds__(256) k_gemm(const float* __restrict__ Xin,
                                              const float* __restrict__ W, int n) {
    __shared__ float xs[64 * 129];
    __shared__ float Wsh[16 * C];
    const float* __restrict__ X = SRC ? (const float*)g_bufB : Xin;
    float* __restrict__ Y = g_bufA;

    const int tid = threadIdx.x;
    const int tx = tid & 15, ty = tid >> 4;
    const int row0 = blockIdx.x * 64;
    constexpr int CC  = C / 16;
    constexpr int CC4 = CC / 4;

    for (int i = tid; i < 64 * 32; i += 256) {
        int r = i >> 5, c4 = i & 31;
        float4 v = make_float4(0.f, 0.f, 0.f, 0.f);
        if (row0 + r < n) v = ((const float4*)X)[(long long)(row0 + r) * 32 + c4];
        float* p = &xs[r * 129 + c4 * 4];
        p[0] = v.x; p[1] = v.y; p[2] = v.z; p[3] = v.w;
    }

    float4 acc[4][CC4];
#pragma unroll
    for (int a = 0; a < 4; a++)
#pragma unroll
        for (int b = 0; b < CC4; b++) acc[a][b] = make_float4(0.f, 0.f, 0.f, 0.f);

    for (int kc = 0; kc < 8; kc++) {
        __syncthreads();
        for (int i = tid; i < 16 * C / 4; i += 256)
            ((float4*)Wsh)[i] = ((const float4*)W)[kc * (16 * C / 4) + i];
        __syncthreads();
#pragma unroll
        for (int k = 0; k < 16; k++) {
            float xr[4];
#pragma unroll
            for (int rr = 0; rr < 4; rr++)
                xr[rr] = xs[(ty + 16 * rr) * 129 + kc * 16 + k];
            float4 wv[CC4];
#pragma unroll
            for (int q = 0; q < CC4; q++)
                wv[q] = *(const float4*)&Wsh[k * C + tx * CC + 4 * q];
#pragma unroll
            for (int rr = 0; rr < 4; rr++)
#pragma unroll
                for (int q = 0; q < CC4; q++) {
                    acc[rr][q].x = fmaf(xr[rr], wv[q].x, acc[rr][q].x);
                    acc[rr][q].y = fmaf(xr[rr], wv[q].y, acc[rr][q].y);
                    acc[rr][q].z = fmaf(xr[rr], wv[q].z, acc[rr][q].z);
                    acc[rr][q].w = fmaf(xr[rr], wv[q].w, acc[rr][q].w);
                }
        }
    }

#pragma unroll
    for (int rr = 0; rr < 4; rr++) {
        int row = row0 + ty + 16 * rr;
        if (row < n) {
#pragma unroll
            for (int q = 0; q < CC4; q++)
                ((float4*)Y)[(long long)row * (C / 4) + tx * CC4 + q] = acc[rr][q];
        }
    }
}

// ---------------- aggregation (fused self-loop + bias + optional ReLU) ----------------
template <bool RELU>
__global__ void __launch_bounds__(256) k_agg128(const float* __restrict__ bias) {
    int warp = (blockIdx.x * 256 + threadIdx.x) >> 5;
    int lane = threadIdx.x & 31;
    if (warp >= NN) return;
    const float4* __restrict__ xw = (const float4*)g_bufA;
    const float d  = g_dinv[warp];
    const float dd = d * d;
    float4 bv  = ((const float4*)bias)[lane];
    float4 acc = xw[(long long)warp * 32 + lane];
    acc.x = fmaf(acc.x, dd, bv.x); acc.y = fmaf(acc.y, dd, bv.y);
    acc.z = fmaf(acc.z, dd, bv.z); acc.w = fmaf(acc.w, dd, bv.w);

    int j = g_rowPtr[warp];
    const int end = g_rowPtr[warp + 1];
    for (; j + 1 < end; j += 2) {
        int s0 = g_csrSrc[j], s1 = g_csrSrc[j + 1];
        float n0 = g_dinv[s0] * d, n1 = g_dinv[s1] * d;
        float4 v0 = xw[(long long)s0 * 32 + lane];
        float4 v1 = xw[(long long)s1 * 32 + lane];
        acc.x += v0.x * n0 + v1.x * n1;
        acc.y += v0.y * n0 + v1.y * n1;
        acc.z += v0.z * n0 + v1.z * n1;
        acc.w += v0.w * n0 + v1.w * n1;
    }
    if (j < end) {
        int s0 = g_csrSrc[j];
        float n0 = g_dinv[s0] * d;
        float4 v0 = xw[(long long)s0 * 32 + lane];
        acc.x += v0.x * n0; acc.y += v0.y * n0;
        acc.z += v0.z * n0; acc.w += v0.w * n0;
    }
    if (RELU) {
        acc.x = fmaxf(acc.x, 0.f); acc.y = fmaxf(acc.y, 0.f);
        acc.z = fmaxf(acc.z, 0.f); acc.w = fmaxf(acc.w, 0.f);
    }
    ((float4*)g_bufB)[(long long)warp * 32 + lane] = acc;
}

__global__ void __launch_bounds__(256) k_agg64(const float* __restrict__ bias) {
    int warp = (blockIdx.x * 256 + threadIdx.x) >> 5;
    int lane = threadIdx.x & 31;
    if (warp >= NN) return;
    const float2* __restrict__ xw = (const float2*)g_bufA;
    const float d  = g_dinv[warp];
    const float dd = d * d;
    float2 bv  = ((const float2*)bias)[lane];
    float2 acc = xw[(long long)warp * 32 + lane];
    acc.x = fmaf(acc.x, dd, bv.x); acc.y = fmaf(acc.y, dd, bv.y);

    int j = g_rowPtr[warp];
    const int end = g_rowPtr[warp + 1];
    for (; j + 1 < end; j += 2) {
        int s0 = g_csrSrc[j], s1 = g_csrSrc[j + 1];
        float n0 = g_dinv[s0] * d, n1 = g_dinv[s1] * d;
        float2 v0 = xw[(long long)s0 * 32 + lane];
        float2 v1 = xw[(long long)s1 * 32 + lane];
        acc.x += v0.x * n0 + v1.x * n1;
        acc.y += v0.y * n0 + v1.y * n1;
    }
    if (j < end) {
        int s0 = g_csrSrc[j];
        float n0 = g_dinv[s0] * d;
        float2 v0 = xw[(long long)s0 * 32 + lane];
        acc.x += v0.x * n0; acc.y += v0.y * n0;
    }
    ((float2*)g_bufB)[(long long)warp * 32 + lane] = acc;
}

// ---------------- sort pool ----------------
__global__ void k_sortpool(float* __restrict__ out) {
    __shared__ float key[PER_GRAPH];
    __shared__ int   sel[POOL_K];
    const int g = blockIdx.x;
    const int tid = threadIdx.x;
    const float* __restrict__ h = g_bufB;

    if (tid < PER_GRAPH)
        key[tid] = h[((long long)(g * PER_GRAPH + tid)) * C3 + (C3 - 1)];
    __syncthreads();

    if (tid < PER_GRAPH) {
        float ki = key[tid];
        int rank = 0;
#pragma unroll 4
        for (int j = 0; j < PER_GRAPH; j++) {
            float kj = key[j];
            rank += (kj > ki) || (kj == ki && j < tid);
        }
        if (rank < POOL_K) sel[rank] = tid;
    }
    __syncthreads();

    for (int t = tid; t < POOL_K * C3; t += blockDim.x) {
        int rank = t / C3, c = t % C3;
        int node = sel[rank];
        out[(long long)g * (POOL_K * C3) + t] =
            h[((long long)(g * PER_GRAPH + node)) * C3 + c];
    }
}

// ---------------- launch ----------------
extern "C" void kernel_launch(void* const* d_in, const int* in_sizes, int n_in,
                              void* d_out, int out_size) {
    const float* x  = (const float*)d_in[0];
    const void*  ei = d_in[1];            // int32 or int64, probed on device
    const float* W1 = (const float*)d_in[3];
    const float* b1 = (const float*)d_in[4];
    const float* W2 = (const float*)d_in[5];
    const float* b2 = (const float*)d_in[6];
    const float* W3 = (const float*)d_in[7];
    const float* b3 = (const float*)d_in[8];
    float* out = (float*)d_out;

    const int n = in_sizes[0] / 128;   // 100000
    const int e = in_sizes[1] / 2;     // 1600000
    const int T = 256;

    // CSR build (chip-wide 3-phase scan)
    k_detect<<<1, 32>>>(ei);
    k_zero_counts<<<(NN + T - 1) / T, T>>>();
    k_count<<<(e + T - 1) / T, T>>>(ei, e);
    k_scanA<<<SCAN_BLKS, 1024>>>();
    k_scanB<<<1, 128>>>(SCAN_BLKS);
    k_scanC<<<(NN + T - 1) / T, T>>>();
    k_fill<<<(e + T - 1) / T, T>>>(ei, e);

    const int gemmBlocks = (n + 63) / 64;
    const int aggBlocks  = (NN * 32 + T - 1) / T;   // warp per node

    // Layer 1: 128 -> 128, relu
    k_gemm<128, 0><<<gemmBlocks, T>>>(x, W1, n);
    k_agg128<true><<<aggBlocks, T>>>(b1);
    // Layer 2: 128 -> 128, relu
    k_gemm<128, 1><<<gemmBlocks, T>>>(nullptr, W2, n);
    k_agg128<true><<<aggBlocks, T>>>(b2);
    // Layer 3: 128 -> 64, no relu
    k_gemm<64, 1><<<gemmBlocks, T>>>(nullptr, W3, n);
    k_agg64<<<aggBlocks, T>>>(b3);

    // Sort pool
    k_sortpool<<<N_GRAPHS, 128>>>(out);
}

// round 9
// speedup vs baseline: 1.3307x; 1.0180x over previous
#include <cuda_runtime.h>

// ---- problem constants ----
#define NN        100000
#define NE        1600000
#define PER_GRAPH 100
#define N_GRAPHS  1000
#define POOL_K    30
#define C3        64
#define SCAN_BLKS ((NN + 1023) / 1024)   // 98
#define MAXDEG    96                     // Poisson(16): P(deg>96) ~ 0

using u64 = unsigned long long;

// ---- device scratch (no allocations allowed) ----
static __device__ float g_bufA[NN * 128];     // GEMM output (xw)
static __device__ float g_bufB[NN * 128];     // layer output
static __device__ float g_dinv[NN];
static __device__ int   g_count[NN];
static __device__ int   g_rowPtr[NN + 1];
static __device__ int   g_cursor[NN];
static __device__ int   g_csrSrc[NE];
static __device__ int   g_csrEid[NE];
static __device__ int   g_bsum[128];
static __device__ int   g_boff[128];
static __device__ int   g_idx64;              // 1 if edge_index is int64, 0 if int32

// ---------------- dtype probe ----------------
__global__ void k_detect(const void* __restrict__ ei) {
    if (threadIdx.x == 0 && blockIdx.x == 0) {
        const int* w = (const int*)ei;
        int is64 = 1;
        for (int i = 0; i < 64; i++)
            if (w[2 * i + 1] != 0) { is64 = 0; break; }
        g_idx64 = is64;
    }
}

__device__ __forceinline__ int edge_at(const void* p, long long i) {
    return g_idx64 ? (int)((const long long*)p)[i] : ((const int*)p)[i];
}

// ---------------- CSR build ----------------
__global__ void k_zero_counts() {
    int i = blockIdx.x * blockDim.x + threadIdx.x;
    if (i < NN) g_count[i] = 0;
}

__global__ void k_count(const void* __restrict__ ei, int e) {
    int i = blockIdx.x * blockDim.x + threadIdx.x;
    if (i >= e) return;
    int d = edge_at(ei, (long long)e + i);   // dst half
    if ((unsigned)d < NN) atomicAdd(&g_count[d], 1);
}

__global__ void __launch_bounds__(1024) k_scanA() {
    __shared__ int s[1024];
    const int tid = threadIdx.x;
    const int i = blockIdx.x * 1024 + tid;
    int c = (i < NN) ? g_count[i] : 0;
    s[tid] = c;
    __syncthreads();
#pragma unroll
    for (int off = 1; off < 1024; off <<= 1) {
        int v = (tid >= off) ? s[tid - off] : 0;
        __syncthreads();
        s[tid] += v;
        __syncthreads();
    }
    if (i < NN) g_rowPtr[i] = s[tid] - c;
    if (tid == 1023) g_bsum[blockIdx.x] = s[1023];
}

__global__ void k_scanB(int nblk) {
    __shared__ int s[128];
    const int tid = threadIdx.x;
    int v = (tid < nblk) ? g_bsum[tid] : 0;
    s[tid] = v;
    __syncthreads();
#pragma unroll
    for (int off = 1; off < 128; off <<= 1) {
        int u = (tid >= off) ? s[tid - off] : 0;
        __syncthreads();
        s[tid] += u;
        __syncthreads();
    }
    if (tid < nblk) g_boff[tid] = s[tid] - v;
    if (tid == 127) g_rowPtr[NN] = s[127];
}

__global__ void k_scanC() {
    int i = blockIdx.x * blockDim.x + threadIdx.x;
    if (i >= NN) return;
    int base = g_rowPtr[i] + g_boff[i >> 10];
    g_rowPtr[i] = base;
    g_cursor[i] = base;
    // IEEE 1/sqrt (matches lax.rsqrt lowering), NOT approximate rsqrtf
    float deg = (float)g_count[i] + 1.0f;    // +1 self-loop
    g_dinv[i] = __fdiv_rn(1.0f, __fsqrt_rn(deg));
}

__global__ void k_fill(const void* __restrict__ ei, int e) {
    int i = blockIdx.x * blockDim.x + threadIdx.x;
    if (i >= e) return;
    int s = edge_at(ei, i);
    int d = edge_at(ei, (long long)e + i);
    if ((unsigned)s >= NN || (unsigned)d >= NN) return;
    int pos = atomicAdd(&g_cursor[d], 1);
    if ((unsigned)pos < NE) { g_csrSrc[pos] = s; g_csrEid[pos] = i; }
}

// Sort each adjacency list by ORIGINAL EDGE ID -> reference's sequential
// scatter order (deterministic, matches segment_sum index order).
__global__ void k_sortadj() {
    int node = blockIdx.x * blockDim.x + threadIdx.x;
    if (node >= NN) return;
    int lo = g_rowPtr[node], hi = g_rowPtr[node + 1];
    int deg = hi - lo;
    if (deg <= 1) return;
    if (deg > MAXDEG) deg = MAXDEG;   // safety; practically never
    u64 v[MAXDEG];
    for (int i = 0; i < deg; i++)
        v[i] = ((u64)(unsigned)g_csrEid[lo + i] << 32) | (unsigned)g_csrSrc[lo + i];
    for (int i = 1; i < deg; i++) {
        u64 key = v[i]; int j = i - 1;
        while (j >= 0 && v[j] > key) { v[j + 1] = v[j]; j--; }
        v[j + 1] = key;
    }
    for (int i = 0; i < deg; i++)
        g_csrSrc[lo + i] = (int)(unsigned)(v[i] & 0xffffffffu);
}

// ---------------- GEMM: bufA[n x C] = X[n x 128] @ W[128 x C] ----------------
// k-ascending fmaf chain (matches FMA-based reference GEMM); W-chunk prefetch.
template <int C, int SRC>   // SRC: 0 = param X, 1 = g_bufB
__global__ void __launch_bounds__(256) k_gemm(const float* __restrict__ Xin,
                                              const float* __restrict__ W, int n) {
    __shared__ float xs[64 * 129];
    __shared__ float Wsh[16 * C];
    const float* __restrict__ X = SRC ? (const float*)g_bufB : Xin;
    float* __restrict__ Y = g_bufA;

    const int tid = threadIdx.x;
    const int tx = tid & 15, ty = tid >> 4;
    const int row0 = blockIdx.x * 64;
    constexpr int CC  = C / 16;
    constexpr int CC4 = CC / 4;
    constexpr int F4  = 4 * C;           // float4s per 16-row W chunk
    constexpr int PF  = F4 / 256;

    for (int i = tid; i < 64 * 32; i += 256) {
        int r = i >> 5, c4 = i & 31;
        float4 v = make_float4(0.f, 0.f, 0.f, 0.f);
        if (row0 + r < n) v = ((const float4*)X)[(long long)(row0 + r) * 32 + c4];
        float* p = &xs[r * 129 + c4 * 4];
        p[0] = v.x; p[1] = v.y; p[2] = v.z; p[3] = v.w;
    }

    const float4* __restrict__ Wg4 = (const float4*)W;
#pragma unroll
    for (int j = 0; j < PF; j++)
        ((float4*)Wsh)[tid + j * 256] = Wg4[tid + j * 256];

    float4 acc[4][CC4];
#pragma unroll
    for (int a = 0; a < 4; a++)
#pragma unroll
        for (int b = 0; b < CC4; b++) acc[a][b] = make_float4(0.f, 0.f, 0.f, 0.f);

    __syncthreads();

    for (int kc = 0; kc < 8; kc++) {
        float4 pre[PF];
        if (kc < 7) {
#pragma unroll
            for (int j = 0; j < PF; j++)
                pre[j] = Wg4[(kc + 1) * F4 + tid + j * 256];
        }
#pragma unroll
        for (int k = 0; k < 16; k++) {
            float xr[4];
#pragma unroll
            for (int rr = 0; rr < 4; rr++)
                xr[rr] = xs[(ty + 16 * rr) * 129 + kc * 16 + k];
            float4 wv[CC4];
#pragma unroll
            for (int q = 0; q < CC4; q++)
                wv[q] = *(const float4*)&Wsh[k * C + tx * CC + 4 * q];
#pragma unroll
            for (int rr = 0; rr < 4; rr++)
#pragma unroll
                for (int q = 0; q < CC4; q++) {
                    acc[rr][q].x = fmaf(xr[rr], wv[q].x, acc[rr][q].x);
                    acc[rr][q].y = fmaf(xr[rr], wv[q].y, acc[rr][q].y);
                    acc[rr][q].z = fmaf(xr[rr], wv[q].z, acc[rr][q].z);
                    acc[rr][q].w = fmaf(xr[rr], wv[q].w, acc[rr][q].w);
                }
        }
        if (kc < 7) {
            __syncthreads();
#pragma unroll
            for (int j = 0; j < PF; j++)
                ((float4*)Wsh)[tid + j * 256] = pre[j];
            __syncthreads();
        }
    }

#pragma unroll
    for (int rr = 0; rr < 4; rr++) {
        int row = row0 + ty + 16 * rr;
        if (row < n) {
#pragma unroll
            for (int q = 0; q < CC4; q++)
                ((float4*)Y)[(long long)row * (C / 4) + tx * CC4 + q] = acc[rr][q];
        }
    }
}

// ---------------- aggregation: reference-exact rounding ----------------
// acc = 0; for edges in ORIGINAL ORDER: acc = add(acc, mul(xw[s], mul(dinv[s],dinv[i])))
// then self-loop: acc = add(acc, mul(xw[i], mul(dinv[i],dinv[i])))
// then bias:      acc = add(acc, b)
// All unfused __fmul_rn/__fadd_rn — matches XLA's elementwise mul + segment_sum.
template <bool RELU>
__global__ void __launch_bounds__(256) k_agg128(const float* __restrict__ bias) {
    int node = (blockIdx.x * 256 + threadIdx.x) >> 5;
    int lane = threadIdx.x & 31;
    if (node >= NN) return;
    const float4* __restrict__ xw = (const float4*)g_bufA;
    const float d = g_dinv[node];

    float4 acc = make_float4(0.f, 0.f, 0.f, 0.f);
    const int lo = g_rowPtr[node], end = g_rowPtr[node + 1];
    for (int j = lo; j < end; j++) {
        int s = g_csrSrc[j];
        float nm = __fmul_rn(g_dinv[s], d);
        float4 v = xw[(long long)s * 32 + lane];
        acc.x = __fadd_rn(acc.x, __fmul_rn(v.x, nm));
        acc.y = __fadd_rn(acc.y, __fmul_rn(v.y, nm));
        acc.z = __fadd_rn(acc.z, __fmul_rn(v.z, nm));
        acc.w = __fadd_rn(acc.w, __fmul_rn(v.w, nm));
    }
    // self-loop last (segment index E+i comes after all edges)
    {
        float dd = __fmul_rn(d, d);
        float4 v = xw[(long long)node * 32 + lane];
        acc.x = __fadd_rn(acc.x, __fmul_rn(v.x, dd));
        acc.y = __fadd_rn(acc.y, __fmul_rn(v.y, dd));
        acc.z = __fadd_rn(acc.z, __fmul_rn(v.z, dd));
        acc.w = __fadd_rn(acc.w, __fmul_rn(v.w, dd));
    }
    // bias last
    {
        float4 bv = ((const float4*)bias)[lane];
        acc.x = __fadd_rn(acc.x, bv.x);
        acc.y = __fadd_rn(acc.y, bv.y);
        acc.z = __fadd_rn(acc.z, bv.z);
        acc.w = __fadd_rn(acc.w, bv.w);
    }
    if (RELU) {
        acc.x = fmaxf(acc.x, 0.f); acc.y = fmaxf(acc.y, 0.f);
        acc.z = fmaxf(acc.z, 0.f); acc.w = fmaxf(acc.w, 0.f);
    }
    ((float4*)g_bufB)[(long long)node * 32 + lane] = acc;
}

__global__ void __launch_bounds__(256) k_agg64(const float* __restrict__ bias) {
    int node = (blockIdx.x * 256 + threadIdx.x) >> 5;
    int lane = threadIdx.x & 31;
    if (node >= NN) return;
    const float2* __restrict__ xw = (const float2*)g_bufA;
    const float d = g_dinv[node];

    float2 acc = make_float2(0.f, 0.f);
    const int lo = g_rowPtr[node], end = g_rowPtr[node + 1];
    for (int j = lo; j < end; j++) {
        int s = g_csrSrc[j];
        float nm = __fmul_rn(g_dinv[s], d);
        float2 v = xw[(long long)s * 32 + lane];
        acc.x = __fadd_rn(acc.x, __fmul_rn(v.x, nm));
        acc.y = __fadd_rn(acc.y, __fmul_rn(v.y, nm));
    }
    {
        float dd = __fmul_rn(d, d);
        float2 v = xw[(long long)node * 32 + lane];
        acc.x = __fadd_rn(acc.x, __fmul_rn(v.x, dd));
        acc.y = __fadd_rn(acc.y, __fmul_rn(v.y, dd));
    }
    {
        float2 bv = ((const float2*)bias)[lane];
        acc.x = __fadd_rn(acc.x, bv.x);
        acc.y = __fadd_rn(acc.y, bv.y);
    }
    ((float2*)g_bufB)[(long long)node * 32 + lane] = acc;
}

// ---------------- sort pool ----------------
__global__ void k_sortpool(float* __restrict__ out) {
    __shared__ float key[PER_GRAPH];
    __shared__ int   sel[POOL_K];
    const int g = blockIdx.x;
    const int tid = threadIdx.x;
    const float* __restrict__ h = g_bufB;

    if (tid < PER_GRAPH)
        key[tid] = h[((long long)(g * PER_GRAPH + tid)) * C3 + (C3 - 1)];
    __syncthreads();

    if (tid < PER_GRAPH) {
        float ki = key[tid];
        int rank = 0;
#pragma unroll 4
        for (int j = 0; j < PER_GRAPH; j++) {
            float kj = key[j];
            rank += (kj > ki) || (kj == ki && j < tid);
        }
        if (rank < POOL_K) sel[rank] = tid;
    }
    __syncthreads();

    for (int t = tid; t < POOL_K * C3; t += blockDim.x) {
        int rank = t / C3, c = t % C3;
        int node = sel[rank];
        out[(long long)g * (POOL_K * C3) + t] =
            h[((long long)(g * PER_GRAPH + node)) * C3 + c];
    }
}

// ---------------- launch ----------------
extern "C" void kernel_launch(void* const* d_in, const int* in_sizes, int n_in,
                              void* d_out, int out_size) {
    const float* x  = (const float*)d_in[0];
    const void*  ei = d_in[1];            // int32 or int64, probed on device
    const float* W1 = (const float*)d_in[3];
    const float* b1 = (const float*)d_in[4];
    const float* W2 = (const float*)d_in[5];
    const float* b2 = (const float*)d_in[6];
    const float* W3 = (const float*)d_in[7];
    const float* b3 = (const float*)d_in[8];
    float* out = (float*)d_out;

    const int n = in_sizes[0] / 128;   // 100000
    const int e = in_sizes[1] / 2;     // 1600000
    const int T = 256;

    // CSR build + canonical edge-id order (reference's sequential semantics)
    k_detect<<<1, 32>>>(ei);
    k_zero_counts<<<(NN + T - 1) / T, T>>>();
    k_count<<<(e + T - 1) / T, T>>>(ei, e);
    k_scanA<<<SCAN_BLKS, 1024>>>();
    k_scanB<<<1, 128>>>(SCAN_BLKS);
    k_scanC<<<(NN + T - 1) / T, T>>>();
    k_fill<<<(e + T - 1) / T, T>>>(ei, e);
    k_sortadj<<<(NN + T - 1) / T, T>>>();

    const int gemmBlocks = (n + 63) / 64;
    const int aggBlocks  = (NN * 32 + T - 1) / T;   // warp per node

    // Layer 1: 128 -> 128, relu
    k_gemm<128, 0><<<gemmBlocks, T>>>(x, W1, n);
    k_agg128<true><<<aggBlocks, T>>>(b1);
    // Layer 2: 128 -> 128, relu
    k_gemm<128, 1><<<gemmBlocks, T>>>(nullptr, W2, n);
    k_agg128<true><<<aggBlocks, T>>>(b2);
    // Layer 3: 128 -> 64, no relu
    k_gemm<64, 1><<<gemmBlocks, T>>>(nullptr, W3, n);
    k_agg64<<<aggBlocks, T>>>(b3);

    // Sort pool
    k_sortpool<<<N_GRAPHS, 128>>>(out);
}

// round 10
// speedup vs baseline: 1.3309x; 1.0002x over previous
#include <cuda_runtime.h>

// ---- problem constants ----
#define NN        100000
#define NE        1600000
#define PER_GRAPH 100
#define N_GRAPHS  1000
#define POOL_K    30
#define C3        64
#define SCAN_BLKS ((NN + 1023) / 1024)   // 98
#define MAXDEG    96                     // Poisson(16): P(deg>96) ~ 0

using u64 = unsigned long long;

// ---- device scratch (no allocations allowed) ----
static __device__ float g_bufA[NN * 128];     // GEMM output (xw)
static __device__ float g_bufB[NN * 128];     // layer output
static __device__ float g_dinv[NN];
static __device__ int   g_count[NN];
static __device__ int   g_rowPtr[NN + 1];
static __device__ int   g_cursor[NN];
static __device__ int   g_csrSrc[NE];
static __device__ int   g_csrEid[NE];
static __device__ int   g_bsum[128];
static __device__ int   g_boff[128];
static __device__ int   g_idx64;              // 1 if edge_index is int64, 0 if int32

// ---------------- packed fp32x2 helpers (sm_103a FFMA2; IEEE .rn per lane) ----------------
__device__ __forceinline__ void ffma2(u64& d, u64 a, u64 b) {
    asm("fma.rn.f32x2 %0, %1, %2, %0;" : "+l"(d) : "l"(a), "l"(b));
}
__device__ __forceinline__ u64 dup2(float x) {
    u64 r;
    asm("mov.b64 %0, {%1, %1};" : "=l"(r) : "f"(x));
    return r;
}

// ---------------- dtype probe ----------------
__global__ void k_detect(const void* __restrict__ ei) {
    if (threadIdx.x == 0 && blockIdx.x == 0) {
        const int* w = (const int*)ei;
        int is64 = 1;
        for (int i = 0; i < 64; i++)
            if (w[2 * i + 1] != 0) { is64 = 0; break; }
        g_idx64 = is64;
    }
}

__device__ __forceinline__ int edge_at(const void* p, long long i) {
    return g_idx64 ? (int)((const long long*)p)[i] : ((const int*)p)[i];
}

// ---------------- CSR build ----------------
__global__ void k_zero_counts() {
    int i = blockIdx.x * blockDim.x + threadIdx.x;
    if (i < NN) g_count[i] = 0;
}

__global__ void k_count(const void* __restrict__ ei, int e) {
    int i = blockIdx.x * blockDim.x + threadIdx.x;
    if (i >= e) return;
    int d = edge_at(ei, (long long)e + i);   // dst half
    if ((unsigned)d < NN) atomicAdd(&g_count[d], 1);
}

__global__ void __launch_bounds__(1024) k_scanA() {
    __shared__ int s[1024];
    const int tid = threadIdx.x;
    const int i = blockIdx.x * 1024 + tid;
    int c = (i < NN) ? g_count[i] : 0;
    s[tid] = c;
    __syncthreads();
#pragma unroll
    for (int off = 1; off < 1024; off <<= 1) {
        int v = (tid >= off) ? s[tid - off] : 0;
        __syncthreads();
        s[tid] += v;
        __syncthreads();
    }
    if (i < NN) g_rowPtr[i] = s[tid] - c;
    if (tid == 1023) g_bsum[blockIdx.x] = s[1023];
}

__global__ void k_scanB(int nblk) {
    __shared__ int s[128];
    const int tid = threadIdx.x;
    int v = (tid < nblk) ? g_bsum[tid] : 0;
    s[tid] = v;
    __syncthreads();
#pragma unroll
    for (int off = 1; off < 128; off <<= 1) {
        int u = (tid >= off) ? s[tid - off] : 0;
        __syncthreads();
        s[tid] += u;
        __syncthreads();
    }
    if (tid < nblk) g_boff[tid] = s[tid] - v;
    if (tid == 127) g_rowPtr[NN] = s[127];
}

__global__ void k_scanC() {
    int i = blockIdx.x * blockDim.x + threadIdx.x;
    if (i >= NN) return;
    int base = g_rowPtr[i] + g_boff[i >> 10];
    g_rowPtr[i] = base;
    g_cursor[i] = base;
    // IEEE 1/sqrt (matches lax.rsqrt lowering), NOT approximate rsqrtf
    float deg = (float)g_count[i] + 1.0f;    // +1 self-loop
    g_dinv[i] = __fdiv_rn(1.0f, __fsqrt_rn(deg));
}

__global__ void k_fill(const void* __restrict__ ei, int e) {
    int i = blockIdx.x * blockDim.x + threadIdx.x;
    if (i >= e) return;
    int s = edge_at(ei, i);
    int d = edge_at(ei, (long long)e + i);
    if ((unsigned)s >= NN || (unsigned)d >= NN) return;
    int pos = atomicAdd(&g_cursor[d], 1);
    if ((unsigned)pos < NE) { g_csrSrc[pos] = s; g_csrEid[pos] = i; }
}

// Sort each adjacency list by ORIGINAL EDGE ID -> reference's sequential
// scatter order (deterministic, matches segment_sum index order).
__global__ void k_sortadj() {
    int node = blockIdx.x * blockDim.x + threadIdx.x;
    if (node >= NN) return;
    int lo = g_rowPtr[node], hi = g_rowPtr[node + 1];
    int deg = hi - lo;
    if (deg <= 1) return;
    if (deg > MAXDEG) deg = MAXDEG;   // safety; practically never
    u64 v[MAXDEG];
    for (int i = 0; i < deg; i++)
        v[i] = ((u64)(unsigned)g_csrEid[lo + i] << 32) | (unsigned)g_csrSrc[lo + i];
    for (int i = 1; i < deg; i++) {
        u64 key = v[i]; int j = i - 1;
        while (j >= 0 && v[j] > key) { v[j + 1] = v[j]; j--; }
        v[j + 1] = key;
    }
    for (int i = 0; i < deg; i++)
        g_csrSrc[lo + i] = (int)(unsigned)(v[i] & 0xffffffffu);
}

// ---------------- GEMM: bufA[n x C] = X[n x 128] @ W[128 x C] ----------------
// k-ascending IEEE fma chain per output (same as R9), packed 2-wide along N
// via fma.rn.f32x2 (bit-exact per lane). W-chunk register prefetch.
template <int C, int SRC>   // SRC: 0 = param X, 1 = g_bufB
__global__ void __launch_bounds__(256) k_gemm(const float* __restrict__ Xin,
                                              const float* __restrict__ W, int n) {
    __shared__ __align__(16) float xs[64 * 129];
    __shared__ __align__(16) float Wsh[16 * C];
    const float* __restrict__ X = SRC ? (const float*)g_bufB : Xin;
    float* __restrict__ Y = g_bufA;

    const int tid = threadIdx.x;
    const int tx = tid & 15, ty = tid >> 4;
    const int row0 = blockIdx.x * 64;
    constexpr int CC  = C / 16;   // cols per thread (8 or 4)
    constexpr int CP  = CC / 2;   // f32x2 pairs per thread (4 or 2)
    constexpr int CQ  = CP / 2;   // 16B (4-float) groups (2 or 1)
    constexpr int F4  = 4 * C;    // float4s per 16-row W chunk
    constexpr int PF  = F4 / 256;

    for (int i = tid; i < 64 * 32; i += 256) {
        int r = i >> 5, c4 = i & 31;
        float4 v = make_float4(0.f, 0.f, 0.f, 0.f);
        if (row0 + r < n) v = ((const float4*)X)[(long long)(row0 + r) * 32 + c4];
        float* p = &xs[r * 129 + c4 * 4];
        p[0] = v.x; p[1] = v.y; p[2] = v.z; p[3] = v.w;
    }

    const float4* __restrict__ Wg4 = (const float4*)W;
#pragma unroll
    for (int j = 0; j < PF; j++)
        ((float4*)Wsh)[tid + j * 256] = Wg4[tid + j * 256];

    u64 acc[4][CP];
#pragma unroll
    for (int a = 0; a < 4; a++)
#pragma unroll
        for (int b = 0; b < CP; b++) acc[a][b] = 0ull;   // (0.f, 0.f)

    __syncthreads();

    for (int kc = 0; kc < 8; kc++) {
        float4 pre[PF];
        if (kc < 7) {
#pragma unroll
            for (int j = 0; j < PF; j++)
                pre[j] = Wg4[(kc + 1) * F4 + tid + j * 256];
        }
#pragma unroll
        for (int k = 0; k < 16; k++) {
            u64 xa[4];
#pragma unroll
            for (int rr = 0; rr < 4; rr++)
                xa[rr] = dup2(xs[(ty + 16 * rr) * 129 + kc * 16 + k]);
            u64 wb[CP];
#pragma unroll
            for (int q = 0; q < CQ; q++) {
                // 16B group q covers floats [tx*CC + 4q, tx*CC + 4q + 4)
                longlong2 wq = *(const longlong2*)&Wsh[k * C + tx * CC + 4 * q];
                wb[2 * q]     = (u64)wq.x;
                wb[2 * q + 1] = (u64)wq.y;
            }
#pragma unroll
            for (int rr = 0; rr < 4; rr++)
#pragma unroll
                for (int p = 0; p < CP; p++)
                    ffma2(acc[rr][p], xa[rr], wb[p]);
        }
        if (kc < 7) {
            __syncthreads();
#pragma unroll
            for (int j = 0; j < PF; j++)
                ((float4*)Wsh)[tid + j * 256] = pre[j];
            __syncthreads();
        }
    }

    union UP { u64 u; float2 f; };
#pragma unroll
    for (int rr = 0; rr < 4; rr++) {
        int row = row0 + ty + 16 * rr;
        if (row < n) {
#pragma unroll
            for (int q = 0; q < CQ; q++) {
                UP a0, a1;
                a0.u = acc[rr][2 * q];
                a1.u = acc[rr][2 * q + 1];
                float4 v = make_float4(a0.f.x, a0.f.y, a1.f.x, a1.f.y);
                ((float4*)Y)[(long long)row * (C / 4) + tx * (CC / 4) + q] = v;
            }
        }
    }
}

// ---------------- aggregation: reference-exact rounding (unchanged from R9) ----------------
template <bool RELU>
__global__ void __launch_bounds__(256) k_agg128(const float* __restrict__ bias) {
    int node = (blockIdx.x * 256 + threadIdx.x) >> 5;
    int lane = threadIdx.x & 31;
    if (node >= NN) return;
    const float4* __restrict__ xw = (const float4*)g_bufA;
    const float d = g_dinv[node];

    float4 acc = make_float4(0.f, 0.f, 0.f, 0.f);
    const int lo = g_rowPtr[node], end = g_rowPtr[node + 1];
    for (int j = lo; j < end; j++) {
        int s = g_csrSrc[j];
        float nm = __fmul_rn(g_dinv[s], d);
        float4 v = xw[(long long)s * 32 + lane];
        acc.x = __fadd_rn(acc.x, __fmul_rn(v.x, nm));
        acc.y = __fadd_rn(acc.y, __fmul_rn(v.y, nm));
        acc.z = __fadd_rn(acc.z, __fmul_rn(v.z, nm));
        acc.w = __fadd_rn(acc.w, __fmul_rn(v.w, nm));
    }
    {
        float dd = __fmul_rn(d, d);
        float4 v = xw[(long long)node * 32 + lane];
        acc.x = __fadd_rn(acc.x, __fmul_rn(v.x, dd));
        acc.y = __fadd_rn(acc.y, __fmul_rn(v.y, dd));
        acc.z = __fadd_rn(acc.z, __fmul_rn(v.z, dd));
        acc.w = __fadd_rn(acc.w, __fmul_rn(v.w, dd));
    }
    {
        float4 bv = ((const float4*)bias)[lane];
        acc.x = __fadd_rn(acc.x, bv.x);
        acc.y = __fadd_rn(acc.y, bv.y);
        acc.z = __fadd_rn(acc.z, bv.z);
        acc.w = __fadd_rn(acc.w, bv.w);
    }
    if (RELU) {
        acc.x = fmaxf(acc.x, 0.f); acc.y = fmaxf(acc.y, 0.f);
        acc.z = fmaxf(acc.z, 0.f); acc.w = fmaxf(acc.w, 0.f);
    }
    ((float4*)g_bufB)[(long long)node * 32 + lane] = acc;
}

__global__ void __launch_bounds__(256) k_agg64(const float* __restrict__ bias) {
    int node = (blockIdx.x * 256 + threadIdx.x) >> 5;
    int lane = threadIdx.x & 31;
    if (node >= NN) return;
    const float2* __restrict__ xw = (const float2*)g_bufA;
    const float d = g_dinv[node];

    float2 acc = make_float2(0.f, 0.f);
    const int lo = g_rowPtr[node], end = g_rowPtr[node + 1];
    for (int j = lo; j < end; j++) {
        int s = g_csrSrc[j];
        float nm = __fmul_rn(g_dinv[s], d);
        float2 v = xw[(long long)s * 32 + lane];
        acc.x = __fadd_rn(acc.x, __fmul_rn(v.x, nm));
        acc.y = __fadd_rn(acc.y, __fmul_rn(v.y, nm));
    }
    {
        float dd = __fmul_rn(d, d);
        float2 v = xw[(long long)node * 32 + lane];
        acc.x = __fadd_rn(acc.x, __fmul_rn(v.x, dd));
        acc.y = __fadd_rn(acc.y, __fmul_rn(v.y, dd));
    }
    {
        float2 bv = ((const float2*)bias)[lane];
        acc.x = __fadd_rn(acc.x, bv.x);
        acc.y = __fadd_rn(acc.y, bv.y);
    }
    ((float2*)g_bufB)[(long long)node * 32 + lane] = acc;
}

// ---------------- sort pool ----------------
__global__ void k_sortpool(float* __restrict__ out) {
    __shared__ float key[PER_GRAPH];
    __shared__ int   sel[POOL_K];
    const int g = blockIdx.x;
    const int tid = threadIdx.x;
    const float* __restrict__ h = g_bufB;

    if (tid < PER_GRAPH)
        key[tid] = h[((long long)(g * PER_GRAPH + tid)) * C3 + (C3 - 1)];
    __syncthreads();

    if (tid < PER_GRAPH) {
        float ki = key[tid];
        int rank = 0;
#pragma unroll 4
        for (int j = 0; j < PER_GRAPH; j++) {
            float kj = key[j];
            rank += (kj > ki) || (kj == ki && j < tid);
        }
        if (rank < POOL_K) sel[rank] = tid;
    }
    __syncthreads();

    for (int t = tid; t < POOL_K * C3; t += blockDim.x) {
        int rank = t / C3, c = t % C3;
        int node = sel[rank];
        out[(long long)g * (POOL_K * C3) + t] =
            h[((long long)(g * PER_GRAPH + node)) * C3 + c];
    }
}

// ---------------- launch ----------------
extern "C" void kernel_launch(void* const* d_in, const int* in_sizes, int n_in,
                              void* d_out, int out_size) {
    const float* x  = (const float*)d_in[0];
    const void*  ei = d_in[1];            // int32 or int64, probed on device
    const float* W1 = (const float*)d_in[3];
    const float* b1 = (const float*)d_in[4];
    const float* W2 = (const float*)d_in[5];
    const float* b2 = (const float*)d_in[6];
    const float* W3 = (const float*)d_in[7];
    const float* b3 = (const float*)d_in[8];
    float* out = (float*)d_out;

    const int n = in_sizes[0] / 128;   // 100000
    const int e = in_sizes[1] / 2;     // 1600000
    const int T = 256;

    // CSR build + canonical edge-id order (reference's sequential semantics)
    k_detect<<<1, 32>>>(ei);
    k_zero_counts<<<(NN + T - 1) / T, T>>>();
    k_count<<<(e + T - 1) / T, T>>>(ei, e);
    k_scanA<<<SCAN_BLKS, 1024>>>();
    k_scanB<<<1, 128>>>(SCAN_BLKS);
    k_scanC<<<(NN + T - 1) / T, T>>>();
    k_fill<<<(e + T - 1) / T, T>>>(ei, e);
    k_sortadj<<<(NN + T - 1) / T, T>>>();

    const int gemmBlocks = (n + 63) / 64;
    const int aggBlocks  = (NN * 32 + T - 1) / T;   // warp per node

    // Layer 1: 128 -> 128, relu
    k_gemm<128, 0><<<gemmBlocks, T>>>(x, W1, n);
    k_agg128<true><<<aggBlocks, T>>>(b1);
    // Layer 2: 128 -> 128, relu
    k_gemm<128, 1><<<gemmBlocks, T>>>(nullptr, W2, n);
    k_agg128<true><<<aggBlocks, T>>>(b2);
    // Layer 3: 128 -> 64, no relu
    k_gemm<64, 1><<<gemmBlocks, T>>>(nullptr, W3, n);
    k_agg64<<<aggBlocks, T>>>(b3);

    // Sort pool
    k_sortpool<<<N_GRAPHS, 128>>>(out);
}